// round 2
// baseline (speedup 1.0000x reference)
#include <cuda_runtime.h>
#include <math.h>

// Problem dims
#define BB 64
#define TT 512
#define DD 512
#define HH 512
#define NG 2048          // 4*H gate columns

// Recurrent kernel partitioning
#define GCTA 128         // persistent CTAs (<=148 -> all co-resident, barrier safe)
#define JW   4           // hidden units per CTA (512/128)
#define GC   16          // gate columns per CTA (4 gates x JW)

// Scratch (device globals: allocation-free per harness rules)
__device__ float g_xw[(size_t)TT * BB * NG];   // [t][r][2048], bias pre-added (268 MB)
__device__ float g_hT[2][HH * BB];             // k-major h: [j][r], double buffered
__device__ unsigned long long g_bar;           // monotone grid barrier counter

__device__ __forceinline__ float sigf(float x) {
    return 1.0f / (1.0f + __expf(-x));
}

// ---------------------------------------------------------------------------
// Kernel 0: per-launch state reset (graph-replay safe)
// ---------------------------------------------------------------------------
__global__ void init_kernel() {
    int idx = blockIdx.x * blockDim.x + threadIdx.x;
    if (idx == 0) g_bar = 0ULL;
    for (int i = idx; i < HH * BB; i += gridDim.x * blockDim.x)
        g_hT[0][i] = 0.0f;
}

// ---------------------------------------------------------------------------
// Kernel 1: g_xw[t*64+r][n] = sum_k x[r][t][k] * W[512+k][n] + b[n]
// Tiled fp32 GEMM. M = 32768 (t-major, r within), N = 2048, K = 512.
// BM=64 (one t per CTA), BN=64, BK=16, 256 threads, 4x4 micro-tile.
// ---------------------------------------------------------------------------
__global__ void __launch_bounds__(256) xw_gemm(const float* __restrict__ x,
                                               const float* __restrict__ W,
                                               const float* __restrict__ bias) {
    __shared__ float As[16][68];  // [k][m], padded: row = 272B (16B aligned)
    __shared__ float Bs[16][64];  // [k][n]

    const int tid = threadIdx.x;
    const int n0  = blockIdx.x * 64;
    const int t   = blockIdx.y;   // m0 = t*64, rows r = 0..63 of batch
    const int ty  = tid >> 4;     // 0..15 (row group)
    const int tx  = tid & 15;     // 0..15 (col group)

    float acc[4][4];
#pragma unroll
    for (int j = 0; j < 4; ++j) {
        float bv = bias[n0 + tx * 4 + j];
#pragma unroll
        for (int i = 0; i < 4; ++i) acc[i][j] = bv;
    }

    // A load ids: 64 rows x 16 k, float4 per thread
    const int ar = tid >> 2;          // batch row 0..63
    const int ak = (tid & 3) * 4;     // k offset 0,4,8,12
    const float* xrow = x + (size_t)ar * (TT * DD) + (size_t)t * DD;
    // B load ids: 16 k x 64 n, float4 per thread
    const int bk = tid >> 4;          // 0..15
    const int bn = (tid & 15) * 4;
    const float* wbase = W + (size_t)(HH + bk) * NG + n0 + bn;

    for (int k0 = 0; k0 < DD; k0 += 16) {
        float4 av = *(const float4*)(xrow + k0 + ak);
        float4 bv = *(const float4*)(wbase + (size_t)k0 * NG);
        __syncthreads();
        As[ak + 0][ar] = av.x;
        As[ak + 1][ar] = av.y;
        As[ak + 2][ar] = av.z;
        As[ak + 3][ar] = av.w;
        *(float4*)&Bs[bk][bn] = bv;
        __syncthreads();
#pragma unroll
        for (int kk = 0; kk < 16; ++kk) {
            float4 a = *(const float4*)&As[kk][ty * 4];
            float4 b = *(const float4*)&Bs[kk][tx * 4];
            acc[0][0] = fmaf(a.x, b.x, acc[0][0]);
            acc[0][1] = fmaf(a.x, b.y, acc[0][1]);
            acc[0][2] = fmaf(a.x, b.z, acc[0][2]);
            acc[0][3] = fmaf(a.x, b.w, acc[0][3]);
            acc[1][0] = fmaf(a.y, b.x, acc[1][0]);
            acc[1][1] = fmaf(a.y, b.y, acc[1][1]);
            acc[1][2] = fmaf(a.y, b.z, acc[1][2]);
            acc[1][3] = fmaf(a.y, b.w, acc[1][3]);
            acc[2][0] = fmaf(a.z, b.x, acc[2][0]);
            acc[2][1] = fmaf(a.z, b.y, acc[2][1]);
            acc[2][2] = fmaf(a.z, b.z, acc[2][2]);
            acc[2][3] = fmaf(a.z, b.w, acc[2][3]);
            acc[3][0] = fmaf(a.w, b.x, acc[3][0]);
            acc[3][1] = fmaf(a.w, b.y, acc[3][1]);
            acc[3][2] = fmaf(a.w, b.z, acc[3][2]);
            acc[3][3] = fmaf(a.w, b.w, acc[3][3]);
        }
    }

    float* dst = g_xw + ((size_t)t * 64) * NG + n0;
#pragma unroll
    for (int i = 0; i < 4; ++i) {
        *(float4*)(dst + (size_t)(ty * 4 + i) * NG + tx * 4) =
            make_float4(acc[i][0], acc[i][1], acc[i][2], acc[i][3]);
    }
}

// ---------------------------------------------------------------------------
// Kernel 2: persistent recurrent LSTM.
// 128 CTAs x 256 threads. Each CTA owns hidden units [J0, J0+4) and their
// 16 gate columns. W_h slice resident in SMEM for the whole sequence; full
// h^T staged to SMEM each step; c-state lives in registers; one software
// grid barrier per step.
// ---------------------------------------------------------------------------
__global__ void __launch_bounds__(256, 1) lstm_rec(const float* __restrict__ W,
                                                   float* __restrict__ out) {
    extern __shared__ float sm[];
    float* sh = sm;                   // 32768 floats: h^T [k][r] (128 KB)
    float* sw = sm + 32768;           // 8192 floats: W_h slice [k][gc] (32 KB)
    float* sz = sm + 32768 + 8192;    // 64*17 floats: z tile, padded

    const int tid = threadIdx.x;
    const int J0  = blockIdx.x * JW;

    // Load W_h slice: sw[k*16+gc] = W[k][ (gc>>2)*512 + J0 + (gc&3) ]
    for (int idx = tid; idx < 512 * GC; idx += 256) {
        int k  = idx >> 4;
        int gc = idx & 15;
        sw[idx] = W[(size_t)k * NG + ((gc >> 2) << 9) + J0 + (gc & 3)];
    }

    // GEMM micro-tile ids: 2 rows x 2 gate-cols per thread
    const int rg = tid >> 3;          // 0..31
    const int cg = tid & 7;           // 0..7
    const int r0 = rg * 2;
    const int c0 = cg * 2;
    const int gcol = ((c0 >> 2) << 9) + J0 + (c0 & 3);  // global gate column of c0

    // Elementwise ids: one (r, jj) pair per thread; contiguous hT writes
    const int jj = tid >> 6;          // 0..3
    const int r  = tid & 63;
    float c = 0.0f;                   // cell state (register-resident all steps)

    __syncthreads();

    for (int t = 0; t < TT; ++t) {
        // Stage h^T_{t-1} (bypass L1: other CTAs wrote it since our last read)
        {
            const float4* src4 = (const float4*)g_hT[t & 1];
            float4* dst4 = (float4*)sh;
#pragma unroll 8
            for (int i = 0; i < 32; ++i)
                dst4[tid + (i << 8)] = __ldcg(src4 + tid + (i << 8));
        }
        __syncthreads();

        // Init accumulators from precomputed x@Wx + b
        const float* xwrow = g_xw + (((size_t)t << 6) + r0) * NG + gcol;
        float2 a0 = *(const float2*)(xwrow);
        float2 a1 = *(const float2*)(xwrow + NG);
        float acc00 = a0.x, acc01 = a0.y, acc10 = a1.x, acc11 = a1.y;

        const float* hp = sh + r0;
        const float* wp = sw + c0;
#pragma unroll 8
        for (int k = 0; k < HH; ++k) {
            float2 hv = *(const float2*)(hp + (k << 6));
            float2 wv = *(const float2*)(wp + (k << 4));
            acc00 = fmaf(hv.x, wv.x, acc00);
            acc01 = fmaf(hv.x, wv.y, acc01);
            acc10 = fmaf(hv.y, wv.x, acc10);
            acc11 = fmaf(hv.y, wv.y, acc11);
        }

        sz[r0 * 17 + c0]           = acc00;
        sz[r0 * 17 + c0 + 1]       = acc01;
        sz[(r0 + 1) * 17 + c0]     = acc10;
        sz[(r0 + 1) * 17 + c0 + 1] = acc11;
        __syncthreads();

        // Gate math: z cols [0..3]=f, [4..7]=i, [8..11]=o, [12..15]=c_bar
        float zf = sz[r * 17 + jj];
        float zi = sz[r * 17 + 4 + jj];
        float zo = sz[r * 17 + 8 + jj];
        float zc = sz[r * 17 + 12 + jj];
        c = sigf(zf) * c + sigf(zi) * zc;
        float h = sigf(zo) * c;

        g_hT[(t + 1) & 1][(J0 + jj) * 64 + r] = h;
        out[(size_t)r * (TT * HH) + (size_t)t * HH + J0 + jj] = h;

        __threadfence();
        __syncthreads();
        if (tid == 0) {
            atomicAdd(&g_bar, 1ULL);
            unsigned long long target = (unsigned long long)(t + 1) * GCTA;
            while (*(volatile unsigned long long*)&g_bar < target) { }
        }
        __syncthreads();
    }
}

// ---------------------------------------------------------------------------
extern "C" void kernel_launch(void* const* d_in, const int* in_sizes, int n_in,
                              void* d_out, int out_size) {
    const float* x = (const float*)d_in[0];   // [64, 512, 512]
    const float* W = (const float*)d_in[1];   // [1024, 2048]
    const float* b = (const float*)d_in[2];   // [2048]
    float* out = (float*)d_out;               // [64, 512, 512]

    init_kernel<<<32, 256>>>();

    dim3 g1(NG / 64, TT);                     // (32, 512)
    xw_gemm<<<g1, 256>>>(x, W, b);

    size_t smem = (size_t)(32768 + 8192 + 64 * 17) * sizeof(float);  // 168192 B
    cudaFuncSetAttribute(lstm_rec, cudaFuncAttributeMaxDynamicSharedMemorySize,
                         (int)smem);
    lstm_rec<<<GCTA, 256, smem>>>(W, out);
}

// round 5
// speedup vs baseline: 1.1618x; 1.1618x over previous
#include <cuda_runtime.h>
#include <cuda_bf16.h>
#include <cstdint>
#include <math.h>

// Problem dims
#define BB 64
#define TT 512
#define DD 512
#define HH 512
#define NG 2048          // 4*H gate columns

// Recurrent kernel partitioning
#define GCTA 128
#define JW   4
#define GC   16

// ---------------------------------------------------------------------------
// Device scratch (allocation-free per harness rules)
// ---------------------------------------------------------------------------
__device__ float g_xw[(size_t)TT * BB * NG];          // [m=t*64+r][2048] fp32
__device__ float g_hT[2][HH * BB];                    // k-major h, double buffered
__device__ unsigned long long g_bar;                  // grid barrier counter
__device__ __nv_bfloat16 g_xhi[(size_t)TT * BB * DD]; // X split hi [32768,512]
__device__ __nv_bfloat16 g_xlo[(size_t)TT * BB * DD]; // X split lo
__device__ __nv_bfloat16 g_wthi[(size_t)NG * DD];     // Wx^T hi [2048,512]
__device__ __nv_bfloat16 g_wtlo[(size_t)NG * DD];     // Wx^T lo

__device__ __forceinline__ float sigf(float x) {
    return 1.0f / (1.0f + __expf(-x));
}

__device__ __forceinline__ uint32_t smem_u32(const void* p) {
    uint32_t a;
    asm("{ .reg .u64 t; cvta.to.shared.u64 t, %1; cvt.u32.u64 %0, t; }"
        : "=r"(a) : "l"(p));
    return a;
}

// ---------------------------------------------------------------------------
// Kernel 0: conversion + per-replay state reset.
// ---------------------------------------------------------------------------
__global__ void __launch_bounds__(256) conv_kernel(const float* __restrict__ x,
                                                   const float* __restrict__ W) {
    const size_t stride = (size_t)gridDim.x * blockDim.x;
    const size_t id0 = (size_t)blockIdx.x * blockDim.x + threadIdx.x;
    if (id0 == 0) g_bar = 0ULL;

    for (size_t i = id0; i < (size_t)TT * BB * DD; i += stride) {
        size_t m = i >> 9;
        int k = (int)(i & 511);
        int t = (int)(m >> 6);
        int r = (int)(m & 63);
        float v = x[(size_t)r * (TT * DD) + (size_t)t * DD + k];
        __nv_bfloat16 hi = __float2bfloat16(v);
        g_xhi[i] = hi;
        g_xlo[i] = __float2bfloat16(v - __bfloat162float(hi));
    }

    for (size_t i = id0; i < (size_t)NG * DD; i += stride) {
        int n = (int)(i & (NG - 1));
        int k = (int)(i >> 11);
        float v = W[(size_t)(HH + k) * NG + n];
        __nv_bfloat16 hi = __float2bfloat16(v);
        g_wthi[(size_t)n * DD + k] = hi;
        g_wtlo[(size_t)n * DD + k] = __float2bfloat16(v - __bfloat162float(hi));
    }

    for (size_t i = id0; i < HH * BB; i += stride) g_hT[0][i] = 0.0f;
}

// ---------------------------------------------------------------------------
// mma.sync helpers (baseline PTX, works on plain sm_103 target)
// ---------------------------------------------------------------------------
__device__ __forceinline__ void ldsm_x4(uint32_t& r0, uint32_t& r1,
                                        uint32_t& r2, uint32_t& r3,
                                        uint32_t addr) {
    asm volatile("ldmatrix.sync.aligned.m8n8.x4.shared.b16 {%0,%1,%2,%3}, [%4];"
                 : "=r"(r0), "=r"(r1), "=r"(r2), "=r"(r3) : "r"(addr));
}
// B tile is stored n-major [n][k]; the m16n8k16 B fragment (thread t holds
// consecutive-k pair at n = t/4) is exactly what NON-trans ldmatrix yields
// when rows = n. (.trans here was the R4 correctness bug.)
__device__ __forceinline__ void ldsm_x2(uint32_t& r0, uint32_t& r1,
                                        uint32_t addr) {
    asm volatile("ldmatrix.sync.aligned.m8n8.x2.shared.b16 {%0,%1}, [%2];"
                 : "=r"(r0), "=r"(r1) : "r"(addr));
}
__device__ __forceinline__ void mma16816(float* c, const uint32_t* a,
                                         const uint32_t* b) {
    asm volatile(
        "mma.sync.aligned.m16n8k16.row.col.f32.bf16.bf16.f32 "
        "{%0,%1,%2,%3}, {%4,%5,%6,%7}, {%8,%9}, {%0,%1,%2,%3};"
        : "+f"(c[0]), "+f"(c[1]), "+f"(c[2]), "+f"(c[3])
        : "r"(a[0]), "r"(a[1]), "r"(a[2]), "r"(a[3]), "r"(b[0]), "r"(b[1]));
}

// ---------------------------------------------------------------------------
// Kernel 1: bf16 3-term split GEMM via mma.sync (tensor pipe).
// g_xw[m][n] = sum_k X[m][k]*Wx[k][n] + b[n], via AhBh + AhBl + AlBh.
// CTA tile 128x128, 8 warps (warp tile 32x64), K chunked x32.
// ---------------------------------------------------------------------------
#define KP 40   // padded smem k-stride (80 B rows: conflict-free ldmatrix)

__global__ void __launch_bounds__(256) xw_mma(const float* __restrict__ bias) {
    __shared__ __nv_bfloat16 sAh[128 * KP];
    __shared__ __nv_bfloat16 sAl[128 * KP];
    __shared__ __nv_bfloat16 sBh[128 * KP];
    __shared__ __nv_bfloat16 sBl[128 * KP];

    const int tid  = threadIdx.x;
    const int wid  = tid >> 5;
    const int lane = tid & 31;

    const int n0 = blockIdx.x * 128;
    const int m0 = blockIdx.y * 128;

    const int wm = (wid & 3) * 32;   // warp m offset within CTA tile
    const int wn = (wid >> 2) * 64;  // warp n offset

    const __nv_bfloat16* xh = g_xhi + (size_t)m0 * DD;
    const __nv_bfloat16* xl = g_xlo + (size_t)m0 * DD;
    const __nv_bfloat16* wh = g_wthi + (size_t)n0 * DD;
    const __nv_bfloat16* wl = g_wtlo + (size_t)n0 * DD;

    float cf[2][8][4];
#pragma unroll
    for (int mt = 0; mt < 2; ++mt)
#pragma unroll
        for (int nt = 0; nt < 8; ++nt)
#pragma unroll
            for (int i = 0; i < 4; ++i) cf[mt][nt][i] = 0.0f;

    // ldmatrix source addresses (within-warp, fixed per thread)
    // A: row = wm + mt*16 + lane%16, col = kk + (lane/16)*8
    const int a_row = lane & 15;
    const int a_col = (lane >> 4) << 3;
    // B (non-trans x2): lanes 0-7 rows n @ kk, lanes 8-15 rows n @ kk+8
    const int b_row = lane & 7;
    const int b_col = ((lane >> 3) & 1) << 3;

    const uint32_t sAh_u = smem_u32(sAh);
    const uint32_t sAl_u = smem_u32(sAl);
    const uint32_t sBh_u = smem_u32(sBh);
    const uint32_t sBl_u = smem_u32(sBl);

    for (int k0 = 0; k0 < DD; k0 += 32) {
        __syncthreads();
        // Stage 4 tiles of [128][32] bf16; 2 x uint4 per thread per tile
#pragma unroll
        for (int i = 0; i < 2; ++i) {
            int idx = tid + (i << 8);
            int row = idx >> 2;
            int q   = idx & 3;
            size_t go = (size_t)row * DD + k0 + q * 8;
            int so = row * KP + q * 8;
            *(uint4*)&sAh[so] = *(const uint4*)(xh + go);
            *(uint4*)&sAl[so] = *(const uint4*)(xl + go);
            *(uint4*)&sBh[so] = *(const uint4*)(wh + go);
            *(uint4*)&sBl[so] = *(const uint4*)(wl + go);
        }
        __syncthreads();

#pragma unroll
        for (int kk = 0; kk < 32; kk += 16) {
            uint32_t ah[2][4], al[2][4], bh[8][2], bl[8][2];
#pragma unroll
            for (int mt = 0; mt < 2; ++mt) {
                uint32_t off =
                    (uint32_t)(((wm + mt * 16 + a_row) * KP + kk + a_col) * 2);
                ldsm_x4(ah[mt][0], ah[mt][1], ah[mt][2], ah[mt][3], sAh_u + off);
                ldsm_x4(al[mt][0], al[mt][1], al[mt][2], al[mt][3], sAl_u + off);
            }
#pragma unroll
            for (int nt = 0; nt < 8; ++nt) {
                uint32_t off =
                    (uint32_t)(((wn + nt * 8 + b_row) * KP + kk + b_col) * 2);
                ldsm_x2(bh[nt][0], bh[nt][1], sBh_u + off);
                ldsm_x2(bl[nt][0], bl[nt][1], sBl_u + off);
            }
#pragma unroll
            for (int nt = 0; nt < 8; ++nt) {
#pragma unroll
                for (int mt = 0; mt < 2; ++mt) {
                    mma16816(cf[mt][nt], ah[mt], bh[nt]);
                    mma16816(cf[mt][nt], ah[mt], bl[nt]);
                    mma16816(cf[mt][nt], al[mt], bh[nt]);
                }
            }
        }
    }

    // Epilogue: c0,c1 -> (row=lane/4, col=2*(lane%4)); c2,c3 -> row+8
    const int er = lane >> 2;
    const int ec = (lane & 3) << 1;
#pragma unroll
    for (int nt = 0; nt < 8; ++nt) {
        int coln = n0 + wn + nt * 8 + ec;
        float2 bv = *(const float2*)(bias + coln);
#pragma unroll
        for (int mt = 0; mt < 2; ++mt) {
            int rowm = m0 + wm + mt * 16 + er;
            float* d0 = g_xw + (size_t)rowm * NG + coln;
            float* d1 = g_xw + (size_t)(rowm + 8) * NG + coln;
            *(float2*)d0 = make_float2(cf[mt][nt][0] + bv.x, cf[mt][nt][1] + bv.y);
            *(float2*)d1 = make_float2(cf[mt][nt][2] + bv.x, cf[mt][nt][3] + bv.y);
        }
    }
}

// ---------------------------------------------------------------------------
// Kernel 2: persistent recurrent LSTM (unchanged from passing R2 version).
// ---------------------------------------------------------------------------
__global__ void __launch_bounds__(256, 1) lstm_rec(const float* __restrict__ W,
                                                   float* __restrict__ out) {
    extern __shared__ float sm[];
    float* sh = sm;                   // 32768 floats: h^T [k][r]
    float* sw = sm + 32768;           // 8192 floats: W_h slice [k][gc]
    float* sz = sm + 32768 + 8192;    // 64*17 z tile

    const int tid = threadIdx.x;
    const int J0  = blockIdx.x * JW;

    for (int idx = tid; idx < 512 * GC; idx += 256) {
        int k  = idx >> 4;
        int gc = idx & 15;
        sw[idx] = W[(size_t)k * NG + ((gc >> 2) << 9) + J0 + (gc & 3)];
    }

    const int rg = tid >> 3;
    const int cg = tid & 7;
    const int r0 = rg * 2;
    const int c0 = cg * 2;
    const int gcol = ((c0 >> 2) << 9) + J0 + (c0 & 3);

    const int jj = tid >> 6;
    const int r  = tid & 63;
    float c = 0.0f;

    __syncthreads();

    for (int t = 0; t < TT; ++t) {
        {
            const float4* src4 = (const float4*)g_hT[t & 1];
            float4* dst4 = (float4*)sh;
#pragma unroll 8
            for (int i = 0; i < 32; ++i)
                dst4[tid + (i << 8)] = __ldcg(src4 + tid + (i << 8));
        }
        __syncthreads();

        const float* xwrow = g_xw + (((size_t)t << 6) + r0) * NG + gcol;
        float2 a0 = *(const float2*)(xwrow);
        float2 a1 = *(const float2*)(xwrow + NG);
        float acc00 = a0.x, acc01 = a0.y, acc10 = a1.x, acc11 = a1.y;

        const float* hp = sh + r0;
        const float* wp = sw + c0;
#pragma unroll 8
        for (int k = 0; k < HH; ++k) {
            float2 hv = *(const float2*)(hp + (k << 6));
            float2 wv = *(const float2*)(wp + (k << 4));
            acc00 = fmaf(hv.x, wv.x, acc00);
            acc01 = fmaf(hv.x, wv.y, acc01);
            acc10 = fmaf(hv.y, wv.x, acc10);
            acc11 = fmaf(hv.y, wv.y, acc11);
        }

        sz[r0 * 17 + c0]           = acc00;
        sz[r0 * 17 + c0 + 1]       = acc01;
        sz[(r0 + 1) * 17 + c0]     = acc10;
        sz[(r0 + 1) * 17 + c0 + 1] = acc11;
        __syncthreads();

        float zf = sz[r * 17 + jj];
        float zi = sz[r * 17 + 4 + jj];
        float zo = sz[r * 17 + 8 + jj];
        float zc = sz[r * 17 + 12 + jj];
        c = sigf(zf) * c + sigf(zi) * zc;
        float h = sigf(zo) * c;

        g_hT[(t + 1) & 1][(J0 + jj) * 64 + r] = h;
        out[(size_t)r * (TT * HH) + (size_t)t * HH + J0 + jj] = h;

        __threadfence();
        __syncthreads();
        if (tid == 0) {
            atomicAdd(&g_bar, 1ULL);
            unsigned long long target = (unsigned long long)(t + 1) * GCTA;
            while (*(volatile unsigned long long*)&g_bar < target) { }
        }
        __syncthreads();
    }
}

// ---------------------------------------------------------------------------
extern "C" void kernel_launch(void* const* d_in, const int* in_sizes, int n_in,
                              void* d_out, int out_size) {
    const float* x = (const float*)d_in[0];   // [64, 512, 512]
    const float* W = (const float*)d_in[1];   // [1024, 2048]
    const float* b = (const float*)d_in[2];   // [2048]
    float* out = (float*)d_out;               // [64, 512, 512]

    conv_kernel<<<1024, 256>>>(x, W);

    dim3 g1(NG / 128, (TT * BB) / 128);       // (16, 256)
    xw_mma<<<g1, 256>>>(b);

    size_t smem = (size_t)(32768 + 8192 + 64 * 17) * sizeof(float);
    cudaFuncSetAttribute(lstm_rec, cudaFuncAttributeMaxDynamicSharedMemorySize,
                         (int)smem);
    lstm_rec<<<GCTA, 256, smem>>>(W, out);
}

// round 6
// speedup vs baseline: 1.8803x; 1.6185x over previous
#include <cuda_runtime.h>
#include <cuda_bf16.h>
#include <cstdint>
#include <math.h>

// Problem dims
#define BB 64
#define TT 512
#define DD 512
#define HH 512
#define NG 2048          // 4*H gate columns

// Recurrent kernel partitioning
#define GCTA 128
#define JW   4
#define GC   16
#define HP   520         // padded bf16 row stride for ldmatrix tiles

// ---------------------------------------------------------------------------
// Device scratch (allocation-free per harness rules)
// ---------------------------------------------------------------------------
__device__ float g_xw[(size_t)TT * BB * NG];          // [m=t*64+r][2048] fp32 (bias incl.)
__device__ unsigned long long g_bar;                  // grid barrier counter
__device__ __nv_bfloat16 g_xhi[(size_t)TT * BB * DD]; // X split hi [32768,512]
__device__ __nv_bfloat16 g_xlo[(size_t)TT * BB * DD]; // X split lo
__device__ __nv_bfloat16 g_wthi[(size_t)NG * DD];     // Wx^T hi [2048,512]
__device__ __nv_bfloat16 g_wtlo[(size_t)NG * DD];     // Wx^T lo
__device__ __nv_bfloat16 g_hbf_hi[2][BB * HH];        // h split hi, [r][k], dbl-buf
__device__ __nv_bfloat16 g_hbf_lo[2][BB * HH];        // h split lo

__device__ __forceinline__ float sigf(float x) {
    return 1.0f / (1.0f + __expf(-x));
}

__device__ __forceinline__ uint32_t smem_u32(const void* p) {
    uint32_t a;
    asm("{ .reg .u64 t; cvta.to.shared.u64 t, %1; cvt.u32.u64 %0, t; }"
        : "=r"(a) : "l"(p));
    return a;
}

// ---------------------------------------------------------------------------
// mma.sync / ldmatrix / cp.async helpers (baseline PTX, plain sm_103 target)
// ---------------------------------------------------------------------------
__device__ __forceinline__ void ldsm_x4(uint32_t& r0, uint32_t& r1,
                                        uint32_t& r2, uint32_t& r3,
                                        uint32_t addr) {
    asm volatile("ldmatrix.sync.aligned.m8n8.x4.shared.b16 {%0,%1,%2,%3}, [%4];"
                 : "=r"(r0), "=r"(r1), "=r"(r2), "=r"(r3) : "r"(addr));
}
__device__ __forceinline__ void ldsm_x2(uint32_t& r0, uint32_t& r1,
                                        uint32_t addr) {
    asm volatile("ldmatrix.sync.aligned.m8n8.x2.shared.b16 {%0,%1}, [%2];"
                 : "=r"(r0), "=r"(r1) : "r"(addr));
}
__device__ __forceinline__ void mma16816(float* c, const uint32_t* a,
                                         const uint32_t* b) {
    asm volatile(
        "mma.sync.aligned.m16n8k16.row.col.f32.bf16.bf16.f32 "
        "{%0,%1,%2,%3}, {%4,%5,%6,%7}, {%8,%9}, {%0,%1,%2,%3};"
        : "+f"(c[0]), "+f"(c[1]), "+f"(c[2]), "+f"(c[3])
        : "r"(a[0]), "r"(a[1]), "r"(a[2]), "r"(a[3]), "r"(b[0]), "r"(b[1]));
}
#define CP_ASYNC16(dst_u32, src_ptr) \
    asm volatile("cp.async.cg.shared.global [%0], [%1], 16;" \
                 :: "r"(dst_u32), "l"(src_ptr))
#define CP_COMMIT() asm volatile("cp.async.commit_group;" ::: "memory")
#define CP_WAIT(N)  asm volatile("cp.async.wait_group %0;" :: "n"(N) : "memory")

// ---------------------------------------------------------------------------
// Kernel 0: conversion + per-replay state reset.
// ---------------------------------------------------------------------------
__global__ void __launch_bounds__(256) conv_kernel(const float* __restrict__ x,
                                                   const float* __restrict__ W) {
    const size_t stride = (size_t)gridDim.x * blockDim.x;
    const size_t id0 = (size_t)blockIdx.x * blockDim.x + threadIdx.x;
    if (id0 == 0) g_bar = 0ULL;

    for (size_t i = id0; i < (size_t)TT * BB * DD; i += stride) {
        size_t m = i >> 9;
        int k = (int)(i & 511);
        int t = (int)(m >> 6);
        int r = (int)(m & 63);
        float v = x[(size_t)r * (TT * DD) + (size_t)t * DD + k];
        __nv_bfloat16 hi = __float2bfloat16(v);
        g_xhi[i] = hi;
        g_xlo[i] = __float2bfloat16(v - __bfloat162float(hi));
    }

    for (size_t i = id0; i < (size_t)NG * DD; i += stride) {
        int n = (int)(i & (NG - 1));
        int k = (int)(i >> 11);
        float v = W[(size_t)(HH + k) * NG + n];
        __nv_bfloat16 hi = __float2bfloat16(v);
        g_wthi[(size_t)n * DD + k] = hi;
        g_wtlo[(size_t)n * DD + k] = __float2bfloat16(v - __bfloat162float(hi));
    }

    for (size_t i = id0; i < BB * HH; i += stride) {
        g_hbf_hi[0][i] = __float2bfloat16(0.0f);
        g_hbf_lo[0][i] = __float2bfloat16(0.0f);
    }
}

// ---------------------------------------------------------------------------
// Kernel 1: bf16 3-term split GEMM via mma.sync (tensor pipe).
// Restructured: B fragments loaded per-nt (live regs ~110), 2 CTAs/SM target.
// ---------------------------------------------------------------------------
#define KP 40   // padded smem k-stride (80 B rows)

__global__ void __launch_bounds__(256, 2) xw_mma(const float* __restrict__ bias) {
    __shared__ __nv_bfloat16 sAh[128 * KP];
    __shared__ __nv_bfloat16 sAl[128 * KP];
    __shared__ __nv_bfloat16 sBh[128 * KP];
    __shared__ __nv_bfloat16 sBl[128 * KP];

    const int tid  = threadIdx.x;
    const int wid  = tid >> 5;
    const int lane = tid & 31;

    const int n0 = blockIdx.x * 128;
    const int m0 = blockIdx.y * 128;

    const int wm = (wid & 3) * 32;
    const int wn = (wid >> 2) * 64;

    const __nv_bfloat16* xh = g_xhi + (size_t)m0 * DD;
    const __nv_bfloat16* xl = g_xlo + (size_t)m0 * DD;
    const __nv_bfloat16* wh = g_wthi + (size_t)n0 * DD;
    const __nv_bfloat16* wl = g_wtlo + (size_t)n0 * DD;

    float cf[2][8][4];
#pragma unroll
    for (int mt = 0; mt < 2; ++mt)
#pragma unroll
        for (int nt = 0; nt < 8; ++nt)
#pragma unroll
            for (int i = 0; i < 4; ++i) cf[mt][nt][i] = 0.0f;

    const int a_row = lane & 15;
    const int a_col = (lane >> 4) << 3;
    const int b_row = lane & 7;
    const int b_col = ((lane >> 3) & 1) << 3;

    const uint32_t sAh_u = smem_u32(sAh);
    const uint32_t sAl_u = smem_u32(sAl);
    const uint32_t sBh_u = smem_u32(sBh);
    const uint32_t sBl_u = smem_u32(sBl);

    for (int k0 = 0; k0 < DD; k0 += 32) {
        __syncthreads();
#pragma unroll
        for (int i = 0; i < 2; ++i) {
            int idx = tid + (i << 8);
            int row = idx >> 2;
            int q   = idx & 3;
            size_t go = (size_t)row * DD + k0 + q * 8;
            int so = row * KP + q * 8;
            *(uint4*)&sAh[so] = *(const uint4*)(xh + go);
            *(uint4*)&sAl[so] = *(const uint4*)(xl + go);
            *(uint4*)&sBh[so] = *(const uint4*)(wh + go);
            *(uint4*)&sBl[so] = *(const uint4*)(wl + go);
        }
        __syncthreads();

#pragma unroll
        for (int kk = 0; kk < 32; kk += 16) {
            uint32_t ah[2][4], al[2][4];
#pragma unroll
            for (int mt = 0; mt < 2; ++mt) {
                uint32_t off =
                    (uint32_t)(((wm + mt * 16 + a_row) * KP + kk + a_col) * 2);
                ldsm_x4(ah[mt][0], ah[mt][1], ah[mt][2], ah[mt][3], sAh_u + off);
                ldsm_x4(al[mt][0], al[mt][1], al[mt][2], al[mt][3], sAl_u + off);
            }
#pragma unroll
            for (int nt = 0; nt < 8; ++nt) {
                uint32_t off =
                    (uint32_t)(((wn + nt * 8 + b_row) * KP + kk + b_col) * 2);
                uint32_t bh2[2], bl2[2];
                ldsm_x2(bh2[0], bh2[1], sBh_u + off);
                ldsm_x2(bl2[0], bl2[1], sBl_u + off);
#pragma unroll
                for (int mt = 0; mt < 2; ++mt) {
                    mma16816(cf[mt][nt], ah[mt], bh2);
                    mma16816(cf[mt][nt], ah[mt], bl2);
                    mma16816(cf[mt][nt], al[mt], bh2);
                }
            }
        }
    }

    const int er = lane >> 2;
    const int ec = (lane & 3) << 1;
#pragma unroll
    for (int nt = 0; nt < 8; ++nt) {
        int coln = n0 + wn + nt * 8 + ec;
        float2 bv = *(const float2*)(bias + coln);
#pragma unroll
        for (int mt = 0; mt < 2; ++mt) {
            int rowm = m0 + wm + mt * 16 + er;
            float* d0 = g_xw + (size_t)rowm * NG + coln;
            float* d1 = g_xw + (size_t)(rowm + 8) * NG + coln;
            *(float2*)d0 = make_float2(cf[mt][nt][0] + bv.x, cf[mt][nt][1] + bv.y);
            *(float2*)d1 = make_float2(cf[mt][nt][2] + bv.x, cf[mt][nt][3] + bv.y);
        }
    }
}

// ---------------------------------------------------------------------------
// Kernel 2: persistent recurrent LSTM, tensor-pipe version.
// 128 CTAs x 256 threads (8 warps). Each CTA owns 4 hidden units (16 gate
// cols). Per step: h [64x512] bf16 hi/lo staged via cp.async in 4 K-chunks
// (overlapped with MMA); each warp computes one m16n8 tile of z via
// mma.sync bf16 3-term split into 3 independent accumulator sets.
// ---------------------------------------------------------------------------
#define LSTM_SMEM (2 * 64 * HP * 2 + 2 * 16 * HP * 2 + 64 * 17 * 4)

__global__ void __launch_bounds__(256, 1) lstm_rec(const float* __restrict__ W,
                                                   float* __restrict__ out) {
    extern __shared__ __align__(16) char smraw[];
    __nv_bfloat16* shh = (__nv_bfloat16*)smraw;     // h hi [64][HP]
    __nv_bfloat16* shl = shh + 64 * HP;             // h lo
    __nv_bfloat16* swh = shl + 64 * HP;             // W_h hi [16][HP]
    __nv_bfloat16* swl = swh + 16 * HP;             // W_h lo
    float* sz = (float*)(swl + 16 * HP);            // z tile [64][17]

    const int tid  = threadIdx.x;
    const int wid  = tid >> 5;
    const int lane = tid & 31;
    const int J0   = blockIdx.x * JW;

    // Convert this CTA's W_h slice to bf16 hi/lo (once).
    for (int idx = tid; idx < 16 * 512; idx += 256) {
        int n = idx >> 9;          // local gate col 0..15
        int k = idx & 511;
        float v = W[(size_t)k * NG + ((n >> 2) << 9) + J0 + (n & 3)];
        __nv_bfloat16 hi = __float2bfloat16(v);
        swh[n * HP + k] = hi;
        swl[n * HP + k] = __float2bfloat16(v - __bfloat162float(hi));
    }
    __syncthreads();

    // Warp tile: m0w in {0,16,32,48}, n0w in {0,8}
    const int m0w = (wid & 3) * 16;
    const int n0w = (wid >> 2) * 8;

    const int a_row = lane & 15;
    const int a_col = (lane >> 4) << 3;
    const int b_row = lane & 7;
    const int b_col = ((lane >> 3) & 1) << 3;

    const uint32_t shh_u = smem_u32(shh);
    const uint32_t shl_u = smem_u32(shl);
    const uint32_t swh_u = smem_u32(swh);
    const uint32_t swl_u = smem_u32(swl);

    // Accumulator-init / epilogue maps
    const int er  = lane >> 2;
    const int ec2 = (lane & 3) << 1;
    const int gc  = n0w + ec2;                       // even; pair contiguous
    const int gcolv = ((gc >> 2) << 9) + J0 + (gc & 3);

    // Gate-math ids
    const int jj = tid >> 6;
    const int r  = tid & 63;
    float cst = 0.0f;

    // Stage map (per chunk): idx = tid + j*256 -> (row, seg)
    __syncthreads();

    for (int t = 0; t < TT; ++t) {
        const __nv_bfloat16* ghi = g_hbf_hi[t & 1];
        const __nv_bfloat16* glo = g_hbf_lo[t & 1];

        // Issue 4 cp.async chunk groups (K chunks of 128)
#pragma unroll
        for (int cch = 0; cch < 4; ++cch) {
#pragma unroll
            for (int j = 0; j < 4; ++j) {
                int idx = tid + (j << 8);
                int row = idx >> 4;
                int seg = idx & 15;
                int eoff = row * HP + cch * 128 + seg * 8;
                int goff = row * 512 + cch * 128 + seg * 8;
                CP_ASYNC16(shh_u + eoff * 2, ghi + goff);
                CP_ASYNC16(shl_u + eoff * 2, glo + goff);
            }
            CP_COMMIT();
        }

        // Init accumulators from precomputed x@Wx + b (overlaps cp.async)
        const float* xwp = g_xw + ((size_t)t * 64 + m0w + er) * NG + gcolv;
        float2 x0 = *(const float2*)xwp;
        float2 x1 = *(const float2*)(xwp + 8 * NG);
        float chh[4] = {x0.x, x0.y, x1.x, x1.y};
        float chl[4] = {0.f, 0.f, 0.f, 0.f};
        float clh[4] = {0.f, 0.f, 0.f, 0.f};

#define LSTM_CHUNK(CCH, WAITN)                                                 \
        {                                                                      \
            CP_WAIT(WAITN);                                                    \
            __syncthreads();                                                   \
            _Pragma("unroll")                                                  \
            for (int ks8 = 0; ks8 < 8; ++ks8) {                                \
                uint32_t aoff = (uint32_t)(((m0w + a_row) * HP +               \
                                 CCH * 128 + ks8 * 16 + a_col) * 2);           \
                uint32_t boff = (uint32_t)(((n0w + b_row) * HP +               \
                                 CCH * 128 + ks8 * 16 + b_col) * 2);           \
                uint32_t ah[4], al[4], bh2[2], bl2[2];                         \
                ldsm_x4(ah[0], ah[1], ah[2], ah[3], shh_u + aoff);             \
                ldsm_x4(al[0], al[1], al[2], al[3], shl_u + aoff);             \
                ldsm_x2(bh2[0], bh2[1], swh_u + boff);                         \
                ldsm_x2(bl2[0], bl2[1], swl_u + boff);                         \
                mma16816(chh, ah, bh2);                                        \
                mma16816(chl, ah, bl2);                                        \
                mma16816(clh, al, bh2);                                        \
            }                                                                  \
        }
        LSTM_CHUNK(0, 3)
        LSTM_CHUNK(1, 2)
        LSTM_CHUNK(2, 1)
        LSTM_CHUNK(3, 0)
#undef LSTM_CHUNK

        // z = sum of the 3 split terms -> smem z tile
        sz[(m0w + er) * 17 + gc]         = chh[0] + chl[0] + clh[0];
        sz[(m0w + er) * 17 + gc + 1]     = chh[1] + chl[1] + clh[1];
        sz[(m0w + er + 8) * 17 + gc]     = chh[2] + chl[2] + clh[2];
        sz[(m0w + er + 8) * 17 + gc + 1] = chh[3] + chl[3] + clh[3];
        __syncthreads();

        // Gate math: cols [0..3]=f, [4..7]=i, [8..11]=o, [12..15]=c_bar
        float zf = sz[r * 17 + jj];
        float zi = sz[r * 17 + 4 + jj];
        float zo = sz[r * 17 + 8 + jj];
        float zc = sz[r * 17 + 12 + jj];
        cst = sigf(zf) * cst + sigf(zi) * zc;
        float h = sigf(zo) * cst;

        out[(size_t)r * (TT * HH) + (size_t)t * HH + J0 + jj] = h;
        __nv_bfloat16 hhi = __float2bfloat16(h);
        __nv_bfloat16 hlo = __float2bfloat16(h - __bfloat162float(hhi));
        g_hbf_hi[(t + 1) & 1][r * 512 + J0 + jj] = hhi;
        g_hbf_lo[(t + 1) & 1][r * 512 + J0 + jj] = hlo;

        __threadfence();
        __syncthreads();
        if (tid == 0) {
            atomicAdd(&g_bar, 1ULL);
            unsigned long long target = (unsigned long long)(t + 1) * GCTA;
            while (*(volatile unsigned long long*)&g_bar < target) { }
        }
        __syncthreads();
    }
}

// ---------------------------------------------------------------------------
extern "C" void kernel_launch(void* const* d_in, const int* in_sizes, int n_in,
                              void* d_out, int out_size) {
    const float* x = (const float*)d_in[0];   // [64, 512, 512]
    const float* W = (const float*)d_in[1];   // [1024, 2048]
    const float* b = (const float*)d_in[2];   // [2048]
    float* out = (float*)d_out;               // [64, 512, 512]

    conv_kernel<<<1024, 256>>>(x, W);

    dim3 g1(NG / 128, (TT * BB) / 128);       // (16, 256)
    xw_mma<<<g1, 256>>>(b);

    cudaFuncSetAttribute(lstm_rec, cudaFuncAttributeMaxDynamicSharedMemorySize,
                         LSTM_SMEM);
    lstm_rec<<<GCTA, 256, LSTM_SMEM>>>(W, out);
}